// round 1
// baseline (speedup 1.0000x reference)
#include <cuda_runtime.h>
#include <math_constants.h>

// attention_FCN: B=512, S=512, F=128, H1=80, H2=40
// Algebra: din@W2 = qpre(b) + f @ Weff(b), Weff = (W2b - W2c) + diag(q_b) @ W2d
// Fused per-batch kernel with online (flash) softmax; facts read once.

#define Bn   512
#define Sn   512
#define Fn   128
#define H1n  80
#define H2n  40
#define TSn  64                 // seq tile
#define NTn  (Sn / TSn)         // 8 tiles
#define FSTRIDE 129             // facts smem row stride (bank-conflict-free)
#define H1STRIDE 81             // h1 smem row stride
#define PADV (-4294967295.0f)   // float(-2^32+1)

__device__ float g_q[Bn * Fn];      // PReLU(query@W1+b1)
__device__ float g_qpre[Bn * H1n];  // b2 + q@(W2a+W2c)

// ---------------------------------------------------------------------------
// Prep: per-batch q and qpre. 512 blocks x 128 threads. ~13M FMA, negligible.
// ---------------------------------------------------------------------------
__global__ __launch_bounds__(128) void prep_kernel(
    const float* __restrict__ query, const float* __restrict__ W1,
    const float* __restrict__ b1,    const float* __restrict__ alpha,
    const float* __restrict__ W2,    const float* __restrict__ b2)
{
    __shared__ float qin[Fn];
    __shared__ float qv[Fn];
    const int b = blockIdx.x, t = threadIdx.x;

    qin[t] = query[b * Fn + t];
    __syncthreads();

    float acc = b1[t];
#pragma unroll 4
    for (int k = 0; k < Fn; k++)
        acc = fmaf(qin[k], W1[k * Fn + t], acc);
    float v = (acc >= 0.f) ? acc : alpha[t] * acc;   // PReLU
    qv[t] = v;
    g_q[b * Fn + t] = v;
    __syncthreads();

    if (t < H1n) {
        float a2 = b2[t];
#pragma unroll 4
        for (int k = 0; k < Fn; k++)
            a2 = fmaf(qv[k], W2[k * H1n + t] + W2[(2 * Fn + k) * H1n + t], a2);
        g_qpre[b * H1n + t] = a2;
    }
}

// ---------------------------------------------------------------------------
// Main fused kernel: one CTA per batch, 256 threads, 2 CTAs/SM.
// ---------------------------------------------------------------------------
__global__ __launch_bounds__(256, 2) void din_kernel(
    const float* __restrict__ facts,
    const int*   __restrict__ mask,
    const float* __restrict__ W2,
    const float* __restrict__ W3,
    const float* __restrict__ b3,
    const float* __restrict__ W4,
    const float* __restrict__ b4,
    float* __restrict__ out)
{
    extern __shared__ float dyn[];
    float* fsm  = dyn;                          // TSn * FSTRIDE  (33 KB)
    float* weff = fsm + TSn * FSTRIDE;          // Fn * H1n       (40 KB)
    float* h1sm = weff + Fn * H1n;              // TSn * H1STRIDE (20.7 KB)
    float* w3sm = h1sm + TSn * H1STRIDE;        // H1n * H2n      (12.8 KB)

    __shared__ float qsm[Fn];
    __shared__ float qprem[H1n];
    __shared__ float w4sm[H2n];
    __shared__ float b3sm[H2n];
    __shared__ float scoresm[TSn];
    __shared__ float wsm[TSn];
    __shared__ float accsm[Fn];
    __shared__ float red[4];
    __shared__ float s_m, s_l, s_scale, s_b4;

    const int b = blockIdx.x;
    const int tid = threadIdx.x;

    if (tid < Fn) { qsm[tid] = g_q[b * Fn + tid]; accsm[tid] = 0.f; }
    if (tid >= 128 && tid < 128 + H1n) qprem[tid - 128] = g_qpre[b * H1n + (tid - 128)];
    if (tid == 0) { s_m = -CUDART_INF_F; s_l = 0.f; s_b4 = b4[0]; }
    for (int i = tid; i < H1n * H2n; i += 256) w3sm[i] = W3[i];
    if (tid < H2n) { w4sm[tid] = W4[tid]; b3sm[tid] = b3[tid]; }
    __syncthreads();

    // Weff[k,h] = (W2b - W2c)[k,h] + q[k] * W2d[k,h]
    for (int i = tid; i < Fn * H1n; i += 256) {
        const int k = i / H1n, h = i - k * H1n;
        const float wbc = W2[(Fn + k) * H1n + h] - W2[(2 * Fn + k) * H1n + h];
        const float wd  = W2[(3 * Fn + k) * H1n + h];
        weff[i] = fmaf(qsm[k], wd, wbc);
    }
    __syncthreads();

    const int tx = tid & 15;   // 16 col-groups of 5 (H1=80)
    const int ty = tid >> 4;   // 16 row-groups of 4 (TS=64)

    for (int t = 0; t < NTn; t++) {
        // ---- load facts tile [TSn, Fn] into padded smem ----
        const float4* fp = (const float4*)(facts + (size_t)(b * Sn + t * TSn) * Fn);
        for (int i = tid; i < TSn * (Fn / 4); i += 256) {
            const int row = i >> 5, c4 = i & 31;
            const float4 v = fp[row * 32 + c4];
            float* d = fsm + row * FSTRIDE + c4 * 4;
            d[0] = v.x; d[1] = v.y; d[2] = v.z; d[3] = v.w;
        }
        __syncthreads();

        // ---- GEMM1: h1 = sigmoid(qpre + f @ Weff), per-thread 4x5 tile ----
        float acc[4][5];
#pragma unroll
        for (int i = 0; i < 4; i++)
#pragma unroll
            for (int j = 0; j < 5; j++)
                acc[i][j] = qprem[tx * 5 + j];
        {
            const float* fr = fsm + (ty * 4) * FSTRIDE;
#pragma unroll 4
            for (int k = 0; k < Fn; k++) {
                float bb[5];
#pragma unroll
                for (int j = 0; j < 5; j++) bb[j] = weff[k * H1n + tx * 5 + j];
#pragma unroll
                for (int i = 0; i < 4; i++) {
                    const float a = fr[i * FSTRIDE + k];
#pragma unroll
                    for (int j = 0; j < 5; j++) acc[i][j] = fmaf(a, bb[j], acc[i][j]);
                }
            }
        }
#pragma unroll
        for (int i = 0; i < 4; i++)
#pragma unroll
            for (int j = 0; j < 5; j++)
                h1sm[(ty * 4 + i) * H1STRIDE + tx * 5 + j] =
                    __fdividef(1.f, 1.f + __expf(-acc[i][j]));
        __syncthreads();

        // ---- GEMM2 + score: 4 threads per seq row, 10 cols each ----
        {
            const int r = tid >> 2, hf = tid & 3;
            float a2[10];
#pragma unroll
            for (int j = 0; j < 10; j++) a2[j] = b3sm[hf * 10 + j];
            const float* hr = h1sm + r * H1STRIDE;
#pragma unroll 2
            for (int k = 0; k < H1n; k++) {
                const float hv = hr[k];
#pragma unroll
                for (int j = 0; j < 10; j++)
                    a2[j] = fmaf(hv, w3sm[k * H2n + hf * 10 + j], a2[j]);
            }
            float p = 0.f;
#pragma unroll
            for (int j = 0; j < 10; j++) {
                const float h2 = __fdividef(1.f, 1.f + __expf(-a2[j]));
                p = fmaf(h2, w4sm[hf * 10 + j], p);
            }
            p += __shfl_xor_sync(0xffffffffu, p, 1);
            p += __shfl_xor_sync(0xffffffffu, p, 2);
            if (hf == 0) {
                const int sg = t * TSn + r;
                const float sc = p + s_b4;
                scoresm[r] = (mask[b * Sn + sg] == 1) ? sc : PADV;
            }
        }
        __syncthreads();

        // ---- online softmax: tile max ----
        if (tid < 32) {
            float m4 = fmaxf(scoresm[tid], scoresm[tid + 32]);
#pragma unroll
            for (int off = 16; off; off >>= 1)
                m4 = fmaxf(m4, __shfl_xor_sync(0xffffffffu, m4, off));
            if (tid == 0) {
                const float nm = fmaxf(s_m, m4);
                s_scale = __expf(s_m - nm);   // exp(-inf)=0 first tile
                s_m = nm;
            }
        }
        __syncthreads();

        // ---- weights, partial sum ----
        const float nm = s_m;
        float wv = 0.f;
        if (tid < TSn) {
            wv = __expf(scoresm[tid] - nm);   // masked: exp(~-4e9) -> 0
            wsm[tid] = wv;
        }
#pragma unroll
        for (int off = 16; off; off >>= 1)
            wv += __shfl_xor_sync(0xffffffffu, wv, off);
        if (tid < TSn && (tid & 31) == 0) red[tid >> 5] = wv;
        __syncthreads();

        const float scale = s_scale;
        if (tid == 0) s_l = s_l * scale + red[0] + red[1];
        if (tid < Fn) {
            float a = accsm[tid] * scale;
            const float* fc = fsm + tid;
#pragma unroll 4
            for (int s = 0; s < TSn; s++)
                a = fmaf(wsm[s], fc[s * FSTRIDE], a);
            accsm[tid] = a;
        }
        __syncthreads();
    }

    if (tid < Fn)
        out[b * Fn + tid] = accsm[tid] / s_l;
}

// ---------------------------------------------------------------------------
extern "C" void kernel_launch(void* const* d_in, const int* in_sizes, int n_in,
                              void* d_out, int out_size)
{
    const float* query = (const float*)d_in[0];
    const float* facts = (const float*)d_in[1];
    const int*   mask  = (const int*)  d_in[2];
    const float* W1    = (const float*)d_in[3];
    const float* b1    = (const float*)d_in[4];
    const float* alpha = (const float*)d_in[5];
    const float* W2    = (const float*)d_in[6];
    const float* b2    = (const float*)d_in[7];
    const float* W3    = (const float*)d_in[8];
    const float* b3    = (const float*)d_in[9];
    const float* W4    = (const float*)d_in[10];
    const float* b4    = (const float*)d_in[11];
    float* out = (float*)d_out;

    const int dyn_smem =
        (TSn * FSTRIDE + Fn * H1n + TSn * H1STRIDE + H1n * H2n) * (int)sizeof(float); // 107520 B
    cudaFuncSetAttribute(din_kernel,
                         cudaFuncAttributeMaxDynamicSharedMemorySize, dyn_smem);

    prep_kernel<<<Bn, 128>>>(query, W1, b1, alpha, W2, b2);
    din_kernel<<<Bn, 256, dyn_smem>>>(facts, mask, W2, W3, b3, W4, b4, out);
}

// round 2
// speedup vs baseline: 1.1527x; 1.1527x over previous
#include <cuda_runtime.h>
#include <math_constants.h>

// attention_FCN: B=512, S=512, F=128, H1=80, H2=40
// din@W2 = qpre(b) + f @ Weff(b),  Weff = (W2b - W2c) + diag(q_b) @ W2d
// Single fused kernel, one CTA per batch, online softmax, facts read once.
// Round 2: k-packed fma.rn.f32x2 + LDS.128 everywhere (k-major weights).

#define Bn   512
#define Sn   512
#define Fn   128
#define H1n  80
#define H2n  40
#define TSn  64                 // seq tile
#define NTn  (Sn / TSn)         // 8 tiles
#define FSTRIDE 132             // facts smem row stride (16B-aligned, conflict-free)
#define WS      132             // weffT row stride (k-major)
#define H1S     84              // h1 smem row stride (k-contig, 16B-aligned)
#define W3S     84              // w3T row stride (k-major)
#define PADV (-4294967295.0f)   // float(-2^32+1)

__device__ __forceinline__ unsigned long long pk2(float lo, float hi) {
    unsigned long long r;
    asm("mov.b64 %0, {%1,%2};" : "=l"(r) : "f"(lo), "f"(hi));
    return r;
}
__device__ __forceinline__ float2 upk2(unsigned long long v) {
    float2 r;
    asm("mov.b64 {%0,%1}, %2;" : "=f"(r.x), "=f"(r.y) : "l"(v));
    return r;
}
#define FMA2(d, a, b) \
    asm("fma.rn.f32x2 %0, %1, %2, %0;" : "+l"(d) : "l"(a), "l"(b))

__device__ __forceinline__ float fsigmoid(float x) {
    return __fdividef(1.f, 1.f + __expf(-x));
}

// ---------------------------------------------------------------------------
__global__ __launch_bounds__(256, 2) void din_kernel(
    const float* __restrict__ query,
    const float* __restrict__ facts,
    const int*   __restrict__ mask,
    const float* __restrict__ W1,
    const float* __restrict__ b1,
    const float* __restrict__ alpha,
    const float* __restrict__ W2,
    const float* __restrict__ b2,
    const float* __restrict__ W3,
    const float* __restrict__ b3,
    const float* __restrict__ W4,
    const float* __restrict__ b4,
    float* __restrict__ out)
{
    extern __shared__ float dyn[];
    float* fsm   = dyn;                         // TSn * FSTRIDE
    float* weffT = fsm + TSn * FSTRIDE;         // H1n * WS   (k-major)
    float* h1sm  = weffT + H1n * WS;            // TSn * H1S
    float* w3T   = h1sm + TSn * H1S;            // H2n * W3S  (k-major)

    __shared__ float qin[Fn];
    __shared__ float qsm[Fn];
    __shared__ float qprem[H1n];
    __shared__ float w4sm[H2n];
    __shared__ float b3sm[H2n];
    __shared__ float scoresm[TSn];
    __shared__ float wsm[TSn];
    __shared__ float accsm[Fn];
    __shared__ float red[4];
    __shared__ float s_m, s_l, s_scale, s_b4;

    const int b = blockIdx.x;
    const int tid = threadIdx.x;

    // ---- prep: load query, consts ----
    if (tid < Fn) { qin[tid] = query[b * Fn + tid]; accsm[tid] = 0.f; }
    if (tid == 0) { s_m = -CUDART_INF_F; s_l = 0.f; s_b4 = b4[0]; }
    if (tid < H2n) { w4sm[tid] = W4[tid]; b3sm[tid] = b3[tid]; }
    // w3T[h2][k] = W3[k][h2]
    for (int i = tid; i < H1n * H2n; i += 256) {
        const int h2 = i % H2n, k = i / H2n;
        w3T[h2 * W3S + k] = W3[i];
    }
    __syncthreads();

    // ---- q = PReLU(query @ W1 + b1) ----
    if (tid < Fn) {
        float a0 = b1[tid], a1 = 0.f, a2 = 0.f, a3 = 0.f;
#pragma unroll 4
        for (int k = 0; k < Fn; k += 4) {
            a0 = fmaf(qin[k + 0], W1[(k + 0) * Fn + tid], a0);
            a1 = fmaf(qin[k + 1], W1[(k + 1) * Fn + tid], a1);
            a2 = fmaf(qin[k + 2], W1[(k + 2) * Fn + tid], a2);
            a3 = fmaf(qin[k + 3], W1[(k + 3) * Fn + tid], a3);
        }
        const float acc = (a0 + a1) + (a2 + a3);
        qsm[tid] = (acc >= 0.f) ? acc : alpha[tid] * acc;
    }
    __syncthreads();

    // ---- qpre[h] = b2[h] + sum_k q[k]*(W2a+W2c)[k,h] ----
    if (tid < H1n) {
        float a0 = b2[tid], a1 = 0.f, a2 = 0.f, a3 = 0.f;
#pragma unroll 2
        for (int k = 0; k < Fn; k += 4) {
            a0 = fmaf(qsm[k+0], W2[(k+0)*H1n + tid] + W2[(2*Fn + k+0)*H1n + tid], a0);
            a1 = fmaf(qsm[k+1], W2[(k+1)*H1n + tid] + W2[(2*Fn + k+1)*H1n + tid], a1);
            a2 = fmaf(qsm[k+2], W2[(k+2)*H1n + tid] + W2[(2*Fn + k+2)*H1n + tid], a2);
            a3 = fmaf(qsm[k+3], W2[(k+3)*H1n + tid] + W2[(2*Fn + k+3)*H1n + tid], a3);
        }
        qprem[tid] = (a0 + a1) + (a2 + a3);
    }

    // ---- weffT[h][k] = (W2b - W2c)[k,h] + q[k]*W2d[k,h]  (k-major) ----
    for (int i = tid; i < Fn * H1n; i += 256) {
        const int k = i / H1n, h = i - k * H1n;
        const float wbc = W2[(Fn + k) * H1n + h] - W2[(2 * Fn + k) * H1n + h];
        const float wd  = W2[(3 * Fn + k) * H1n + h];
        weffT[h * WS + k] = fmaf(qsm[k], wd, wbc);
    }
    __syncthreads();

    const int tx = tid & 15;   // 16 col-groups of 5 (H1=80)
    const int ty = tid >> 4;   // 16 row-groups of 4 (TS=64)

    for (int t = 0; t < NTn; t++) {
        // ---- load facts tile [TSn, Fn] into padded smem (float4) ----
        const float4* fp = (const float4*)(facts + (size_t)(b * Sn + t * TSn) * Fn);
        for (int i = tid; i < TSn * (Fn / 4); i += 256) {
            const int row = i >> 5, c4 = i & 31;
            const float4 v = fp[row * 32 + c4];
            *(float4*)(fsm + row * FSTRIDE + c4 * 4) = v;
        }
        __syncthreads();

        // ---- GEMM1: h1 = sigmoid(qpre + f @ Weff), 4x5 per thread, f32x2 ----
        {
            unsigned long long acc2[4][5];
#pragma unroll
            for (int i = 0; i < 4; i++)
#pragma unroll
                for (int j = 0; j < 5; j++)
                    acc2[i][j] = pk2(qprem[tx * 5 + j], 0.f);

            const float* fr = fsm   + (ty * 4) * FSTRIDE;
            const float* wb = weffT + (tx * 5) * WS;
#pragma unroll 2
            for (int k = 0; k < Fn; k += 4) {
                ulonglong2 av[4], bv[5];
#pragma unroll
                for (int i = 0; i < 4; i++)
                    av[i] = *(const ulonglong2*)(fr + i * FSTRIDE + k);
#pragma unroll
                for (int j = 0; j < 5; j++)
                    bv[j] = *(const ulonglong2*)(wb + j * WS + k);
#pragma unroll
                for (int i = 0; i < 4; i++)
#pragma unroll
                    for (int j = 0; j < 5; j++) {
                        FMA2(acc2[i][j], av[i].x, bv[j].x);
                        FMA2(acc2[i][j], av[i].y, bv[j].y);
                    }
            }
#pragma unroll
            for (int i = 0; i < 4; i++)
#pragma unroll
                for (int j = 0; j < 5; j++) {
                    const float2 v = upk2(acc2[i][j]);
                    h1sm[(ty * 4 + i) * H1S + tx * 5 + j] = fsigmoid(v.x + v.y);
                }
        }
        __syncthreads();

        // ---- GEMM2 + score: 4 threads/row x 10 cols, f32x2 ----
        {
            const int r = tid >> 2, hf = tid & 3;
            unsigned long long acc2[10];
#pragma unroll
            for (int j = 0; j < 10; j++) acc2[j] = pk2(b3sm[hf * 10 + j], 0.f);

            const float* hr = h1sm + r * H1S;
            const float* wc = w3T + (hf * 10) * W3S;
#pragma unroll 2
            for (int k = 0; k < H1n; k += 4) {
                const ulonglong2 hv = *(const ulonglong2*)(hr + k);
#pragma unroll
                for (int j = 0; j < 10; j++) {
                    const ulonglong2 wv = *(const ulonglong2*)(wc + j * W3S + k);
                    FMA2(acc2[j], hv.x, wv.x);
                    FMA2(acc2[j], hv.y, wv.y);
                }
            }
            float p = 0.f;
#pragma unroll
            for (int j = 0; j < 10; j++) {
                const float2 v = upk2(acc2[j]);
                p = fmaf(fsigmoid(v.x + v.y), w4sm[hf * 10 + j], p);
            }
            p += __shfl_xor_sync(0xffffffffu, p, 1);
            p += __shfl_xor_sync(0xffffffffu, p, 2);
            if (hf == 0) {
                const int sg = t * TSn + r;
                const float sc = p + s_b4;
                scoresm[r] = (mask[b * Sn + sg] == 1) ? sc : PADV;
            }
        }
        __syncthreads();

        // ---- online softmax: tile max ----
        if (tid < 32) {
            float m4 = fmaxf(scoresm[tid], scoresm[tid + 32]);
#pragma unroll
            for (int off = 16; off; off >>= 1)
                m4 = fmaxf(m4, __shfl_xor_sync(0xffffffffu, m4, off));
            if (tid == 0) {
                const float nm = fmaxf(s_m, m4);
                s_scale = __expf(s_m - nm);   // exp(-inf)=0 on first tile
                s_m = nm;
            }
        }
        __syncthreads();

        // ---- weights, running sum, weighted accumulation ----
        const float nm = s_m;
        float wv = 0.f;
        if (tid < TSn) {
            wv = __expf(scoresm[tid] - nm);
            wsm[tid] = wv;
        }
#pragma unroll
        for (int off = 16; off; off >>= 1)
            wv += __shfl_xor_sync(0xffffffffu, wv, off);
        if (tid < TSn && (tid & 31) == 0) red[tid >> 5] = wv;
        __syncthreads();

        const float scale = s_scale;
        if (tid == 0) s_l = s_l * scale + red[0] + red[1];
        if (tid < Fn) {
            float a = accsm[tid] * scale;
            const float* fc = fsm + tid;
#pragma unroll 8
            for (int s = 0; s < TSn; s++)
                a = fmaf(wsm[s], fc[s * FSTRIDE], a);
            accsm[tid] = a;
        }
        __syncthreads();
    }

    if (tid < Fn)
        out[b * Fn + tid] = accsm[tid] / s_l;
}

// ---------------------------------------------------------------------------
extern "C" void kernel_launch(void* const* d_in, const int* in_sizes, int n_in,
                              void* d_out, int out_size)
{
    const float* query = (const float*)d_in[0];
    const float* facts = (const float*)d_in[1];
    const int*   mask  = (const int*)  d_in[2];
    const float* W1    = (const float*)d_in[3];
    const float* b1    = (const float*)d_in[4];
    const float* alpha = (const float*)d_in[5];
    const float* W2    = (const float*)d_in[6];
    const float* b2    = (const float*)d_in[7];
    const float* W3    = (const float*)d_in[8];
    const float* b3    = (const float*)d_in[9];
    const float* W4    = (const float*)d_in[10];
    const float* b4    = (const float*)d_in[11];
    float* out = (float*)d_out;

    const int dyn_smem =
        (TSn * FSTRIDE + H1n * WS + TSn * H1S + H2n * W3S) * (int)sizeof(float); // 110976 B
    cudaFuncSetAttribute(din_kernel,
                         cudaFuncAttributeMaxDynamicSharedMemorySize, dyn_smem);

    din_kernel<<<Bn, 256, dyn_smem>>>(query, facts, mask, W1, b1, alpha,
                                      W2, b2, W3, b3, W4, b4, out);
}